// round 8
// baseline (speedup 1.0000x reference)
#include <cuda_runtime.h>
#include <math.h>
#include <stdint.h>

typedef unsigned long long ull;

#define SS 512
#define NBLK 128

// ---------------- device scratch (no allocations allowed) ----------------
__device__ float g_WTenc[2048 * 4096];   // packed [k][n'=4j+g]; rows 0..1023 = Wih, 1024..2047 = Whh
__device__ float g_WTdec[2048 * 4096];   // same packing
__device__ float g_WTfc [1024 * 1024];   // plain [k][n]
__device__ float g_gatesX[(size_t)512 * 4096 * 64]; // [t][n'][b]  (512MB)
__device__ float g_dAT[2][2048 * 64];    // ping-pong, [k][b]: k 0..1023 = inp, 1024..2047 = h
__device__ float g_c  [1024 * 64];       // [j][b]
__device__ float g_partG[4][4096 * 64];  // gate partials [kz][n'][b]
__device__ float g_bpe[4096], g_bpd[4096];
__device__ int   g_mask[512];
__device__ unsigned           g_barLeaf[16 * 32];   // one leaf per 128B line
__device__ unsigned           g_barRoot;
__device__ volatile unsigned  g_barGen;

// ---------------- f32x2 helpers ----------------
__device__ __forceinline__ ull dup2(float v) {
    ull r; unsigned u = __float_as_uint(v);
    asm("mov.b64 %0, {%1, %1};" : "=l"(r) : "r"(u));
    return r;
}
__device__ __forceinline__ void fma2(ull& acc, ull a, ull b) {
    asm("fma.rn.f32x2 %0, %1, %2, %0;" : "+l"(acc) : "l"(a), "l"(b));
}
__device__ __forceinline__ ull add2(ull a, ull b) {
    ull r; asm("add.rn.f32x2 %0, %1, %2;" : "=l"(r) : "l"(a), "l"(b)); return r;
}
__device__ __forceinline__ float2 unpack2(ull v) {
    unsigned lo, hi;
    asm("mov.b64 {%0, %1}, %2;" : "=r"(lo), "=r"(hi) : "l"(v));
    return make_float2(__uint_as_float(lo), __uint_as_float(hi));
}
__device__ __forceinline__ float sigf(float x) { return 1.0f / (1.0f + expf(-x)); }

// ---------------- grid barrier: padded-leaf tree arrival + volatile poll ----------------
__device__ __forceinline__ void grid_sync(unsigned n) {
    __syncthreads();
    if (threadIdx.x == 0) {
        __threadfence();
        unsigned leaf = (blockIdx.x >> 3) * 32;          // 16 leaves, 128B apart
        if (atomicAdd(&g_barLeaf[leaf], 1u) + 1u == n * 8u) {
            if (atomicAdd(&g_barRoot, 1u) + 1u == n * 16u) {
                g_barGen = n;
            }
        }
        while (g_barGen < n) { }
        __threadfence();
    }
    __syncthreads();
}

// ============ gate GEMM: tile 64b x 128n, per-CTA K-slice, direct partial store ============
// 256 threads: ty=tid>>5 -> 8 b (4 pairs), tx=tid&31 -> 4 cols. 16 fma2/kk.
__device__ __forceinline__ void gemm_gate(const float* __restrict__ A,    // [k][64] at slice base
                                          const float* __restrict__ Wp,  // + row/col offsets, ldw 4096
                                          int nKT,
                                          float* As, float* Ws,
                                          float* __restrict__ dst,        // g_partG[kz] + p*128*64
                                          int tid)
{
    const int ty = tid >> 5, tx = tid & 31;
    ull acc[4][4];
#pragma unroll
    for (int q = 0; q < 4; ++q)
#pragma unroll
        for (int c = 0; c < 4; ++c) acc[q][c] = 0ull;

    float4 pa[2], pw[4];
#pragma unroll
    for (int i = 0; i < 2; ++i) {
        int idx = tid + i * 256;
        pa[i] = *(const float4*)(A + (size_t)(idx >> 4) * 64 + (idx & 15) * 4);
    }
#pragma unroll
    for (int i = 0; i < 4; ++i) {
        int idx = tid + i * 256;
        pw[i] = *(const float4*)(Wp + (size_t)(idx >> 5) * 4096 + (idx & 31) * 4);
    }

    for (int kt = 0; kt < nKT; ++kt) {
#pragma unroll
        for (int i = 0; i < 2; ++i) {
            int idx = tid + i * 256;
            *(float4*)&As[(idx >> 4) * 64 + (idx & 15) * 4] = pa[i];
        }
#pragma unroll
        for (int i = 0; i < 4; ++i) {
            int idx = tid + i * 256;
            *(float4*)&Ws[(idx >> 5) * 128 + (idx & 31) * 4] = pw[i];
        }
        __syncthreads();
        if (kt + 1 < nKT) {
            int kOff = (kt + 1) * 32;
#pragma unroll
            for (int i = 0; i < 2; ++i) {
                int idx = tid + i * 256;
                pa[i] = *(const float4*)(A + (size_t)(kOff + (idx >> 4)) * 64 + (idx & 15) * 4);
            }
#pragma unroll
            for (int i = 0; i < 4; ++i) {
                int idx = tid + i * 256;
                pw[i] = *(const float4*)(Wp + (size_t)(kOff + (idx >> 5)) * 4096 + (idx & 31) * 4);
            }
        }
#pragma unroll
        for (int kk = 0; kk < 32; ++kk) {
            ulonglong2 aa = *(const ulonglong2*)&As[kk * 64 + 8 * ty];
            ulonglong2 ab = *(const ulonglong2*)&As[kk * 64 + 8 * ty + 4];
            float4 wv = *(const float4*)&Ws[kk * 128 + 4 * tx];
            ull w0 = dup2(wv.x), w1 = dup2(wv.y), w2 = dup2(wv.z), w3 = dup2(wv.w);
            fma2(acc[0][0], aa.x, w0); fma2(acc[0][1], aa.x, w1);
            fma2(acc[0][2], aa.x, w2); fma2(acc[0][3], aa.x, w3);
            fma2(acc[1][0], aa.y, w0); fma2(acc[1][1], aa.y, w1);
            fma2(acc[1][2], aa.y, w2); fma2(acc[1][3], aa.y, w3);
            fma2(acc[2][0], ab.x, w0); fma2(acc[2][1], ab.x, w1);
            fma2(acc[2][2], ab.x, w2); fma2(acc[2][3], ab.x, w3);
            fma2(acc[3][0], ab.y, w0); fma2(acc[3][1], ab.y, w1);
            fma2(acc[3][2], ab.y, w2); fma2(acc[3][3], ab.y, w3);
        }
        __syncthreads();
    }
    // direct store: dst[(localcol)*64 + b], float2 over b-pair
#pragma unroll
    for (int q = 0; q < 4; ++q)
#pragma unroll
        for (int c = 0; c < 4; ++c) {
            float2 v = unpack2(acc[q][c]);
            *(float2*)&dst[(4 * tx + c) * 64 + 8 * ty + 2 * q] = v;
        }
}

// ============ fc GEMM full-K (64b x 8n per CTA) with fused select epilogue ============
__device__ __forceinline__ void fc_select(const float* __restrict__ A,   // h: [k][64], K=1024
                                          const float* __restrict__ Wp, // g_WTfc + bid*8
                                          const float* __restrict__ fc_b,
                                          const float* __restrict__ target,
                                          float* __restrict__ out,
                                          float* __restrict__ dA1,
                                          int t, int bid, int mk,
                                          float* As, float* Ws, int tid)
{
    const int ty = tid >> 3;   // b-pair 0..31
    const int tx = tid & 7;    // col
    ull acc[4];
#pragma unroll
    for (int i = 0; i < 4; ++i) acc[i] = 0ull;

    float4 pa[2], pw;
#pragma unroll
    for (int i = 0; i < 2; ++i) {
        int idx = tid + i * 256;
        pa[i] = *(const float4*)(A + (size_t)(idx >> 4) * 64 + (idx & 15) * 4);
    }
    if (tid < 64)
        pw = *(const float4*)(Wp + (size_t)(tid >> 1) * 1024 + (tid & 1) * 4);

    for (int kt = 0; kt < 32; ++kt) {
#pragma unroll
        for (int i = 0; i < 2; ++i) {
            int idx = tid + i * 256;
            *(float4*)&As[(idx >> 4) * 64 + (idx & 15) * 4] = pa[i];
        }
        if (tid < 64) *(float4*)&Ws[(tid >> 1) * 8 + (tid & 1) * 4] = pw;
        __syncthreads();
        if (kt + 1 < 32) {
            int kOff = (kt + 1) * 32;
#pragma unroll
            for (int i = 0; i < 2; ++i) {
                int idx = tid + i * 256;
                pa[i] = *(const float4*)(A + (size_t)(kOff + (idx >> 4)) * 64 + (idx & 15) * 4);
            }
            if (tid < 64)
                pw = *(const float4*)(Wp + (size_t)(kOff + (tid >> 1)) * 1024 + (tid & 1) * 4);
        }
#pragma unroll
        for (int kk = 0; kk < 32; ++kk) {
            ull a = *(const ull*)&As[kk * 64 + 2 * ty];
            fma2(acc[kk & 3], a, dup2(Ws[kk * 8 + tx]));
        }
        __syncthreads();
    }
    ull s = add2(add2(acc[0], acc[1]), add2(acc[2], acc[3]));
    float2 v = unpack2(s);
    int n = bid * 8 + tx;
    float vb = fc_b[n];
    int b0 = 2 * ty;
    float p0 = v.x + vb, p1 = v.y + vb;
    size_t o0 = ((size_t)b0 * SS + t) * 1024 + n;
    size_t o1 = o0 + (size_t)SS * 1024;
    out[o0] = p0;
    out[o1] = p1;
    dA1[n * 64 + b0]     = mk ? target[o0] : p0;
    dA1[n * 64 + b0 + 1] = mk ? target[o1] : p1;
}

// ============ the persistent seq2seq kernel ============
__global__ __launch_bounds__(256, 1)
void seq2seq_persist(const float* __restrict__ x, const float* __restrict__ target,
                     const float* __restrict__ fc_b, float* __restrict__ out)
{
    __shared__ __align__(16) float As[32 * 64];
    __shared__ __align__(16) float Ws[32 * 128];

    const int tid = threadIdx.x;
    const int bid = blockIdx.x;
    const int p   = bid >> 2;     // n-tile (128 cols)
    const int kz  = bid & 3;      // K quarter
    int cur = 0;
    unsigned ns = 0;

    // ---------------- encoder (gate K=1024, h only; x-part precomputed) ----------------
    for (int t = 0; t < SS; ++t) {
        gemm_gate(g_dAT[cur] + (size_t)(1024 + kz * 256) * 64,
                  g_WTenc + (size_t)(1024 + kz * 256) * 4096 + p * 128,
                  8, As, Ws, g_partG[kz] + (size_t)p * 128 * 64, tid);
        grid_sync(++ns);
#pragma unroll
        for (int r = 0; r < 2; ++r) {
            int id = tid + 256 * r;
            int b = id & 63, jj = id >> 6;
            int np = bid * 32 + 4 * jj;
            int j  = bid * 8 + jj;
            const float* q0 = g_partG[0] + (size_t)np * 64 + b;
            const float* q1 = g_partG[1] + (size_t)np * 64 + b;
            const float* q2 = g_partG[2] + (size_t)np * 64 + b;
            const float* q3 = g_partG[3] + (size_t)np * 64 + b;
            const float* gx = g_gatesX + ((size_t)t * 4096 + np) * 64 + b;
            float4 bb = *(const float4*)&g_bpe[np];
            float gi = q0[0]   + q1[0]   + q2[0]   + q3[0]   + gx[0]   + bb.x;
            float gf = q0[64]  + q1[64]  + q2[64]  + q3[64]  + gx[64]  + bb.y;
            float gg = q0[128] + q1[128] + q2[128] + q3[128] + gx[128] + bb.z;
            float go = q0[192] + q1[192] + q2[192] + q3[192] + gx[192] + bb.w;
            float c  = g_c[j * 64 + b];
            float cn = sigf(gf) * c + sigf(gi) * tanhf(gg);
            float hn = sigf(go) * tanhf(cn);
            g_c[j * 64 + b] = cn;
            g_dAT[cur ^ 1][(1024 + j) * 64 + b] = hn;
            if (t == SS - 1)   // stage dec_inp0 = x[:, -1, :]
                g_dAT[cur ^ 1][j * 64 + b] = x[((size_t)b * SS + SS - 1) * 1024 + j];
        }
        grid_sync(++ns);
        cur ^= 1;
    }

    // ---------------- decoder (gate K=2048) ----------------
    for (int t = 0; t < SS; ++t) {
        gemm_gate(g_dAT[cur] + (size_t)(kz * 512) * 64,
                  g_WTdec + (size_t)(kz * 512) * 4096 + p * 128,
                  16, As, Ws, g_partG[kz] + (size_t)p * 128 * 64, tid);
        grid_sync(++ns);
#pragma unroll
        for (int r = 0; r < 2; ++r) {
            int id = tid + 256 * r;
            int b = id & 63, jj = id >> 6;
            int np = bid * 32 + 4 * jj;
            int j  = bid * 8 + jj;
            const float* q0 = g_partG[0] + (size_t)np * 64 + b;
            const float* q1 = g_partG[1] + (size_t)np * 64 + b;
            const float* q2 = g_partG[2] + (size_t)np * 64 + b;
            const float* q3 = g_partG[3] + (size_t)np * 64 + b;
            float4 bb = *(const float4*)&g_bpd[np];
            float gi = q0[0]   + q1[0]   + q2[0]   + q3[0]   + bb.x;
            float gf = q0[64]  + q1[64]  + q2[64]  + q3[64]  + bb.y;
            float gg = q0[128] + q1[128] + q2[128] + q3[128] + bb.z;
            float go = q0[192] + q1[192] + q2[192] + q3[192] + bb.w;
            float c  = g_c[j * 64 + b];
            float cn = sigf(gf) * c + sigf(gi) * tanhf(gg);
            float hn = sigf(go) * tanhf(cn);
            g_c[j * 64 + b] = cn;
            g_dAT[cur ^ 1][(1024 + j) * 64 + b] = hn;
        }
        grid_sync(++ns);   // h complete before fc reads full K
        fc_select(g_dAT[cur ^ 1] + (size_t)1024 * 64, g_WTfc + bid * 8,
                  fc_b, target, out, g_dAT[cur ^ 1], t, bid, g_mask[t], As, Ws, tid);
        grid_sync(++ns);   // inp visible before next gate GEMM
        cur ^= 1;
    }
}

// ============ pre-GEMM: gatesX[t][n'][b] = x[b,t,:] @ packed Wih^T ============
// tile 128m x 128n (m = 2 timesteps x 64 batch), per-thread 8x8 = 32 fma2/kk
__global__ __launch_bounds__(256, 1)
void gemm_pre(const float* __restrict__ x, const float* __restrict__ W,
              float* __restrict__ C)
{
    __shared__ __align__(16) float As[32 * 128];   // [k][m] swizzled
    __shared__ __align__(16) float Ws[32 * 128];   // [k][n]

    const int tid = threadIdx.x;
    const int nBase = blockIdx.x * 128;
    const int tp    = blockIdx.y;          // t-pair
    const int tyy = tid >> 4;              // 0..15 -> pairs {tyy, tyy+16, tyy+32, tyy+48}
    const int tx  = tid & 15;              // cols 8*tx .. 8*tx+7

    ull acc[4][8];
#pragma unroll
    for (int s = 0; s < 4; ++s)
#pragma unroll
        for (int c = 0; c < 8; ++c) acc[s][c] = 0ull;

    // row pointers for the 4 A-load rows this thread stages
    const float* rp[4];
#pragma unroll
    for (int i = 0; i < 4; ++i) {
        int idx = tid + i * 256;
        int mA = idx >> 3;
        int b = mA & 63, tsel = mA >> 6;
        rp[i] = x + ((size_t)b * SS + 2 * tp + tsel) * 1024;
    }
    const int k4 = tid & 7;

    float4 pa[4], pw[4];
#pragma unroll
    for (int i = 0; i < 4; ++i) {
        pa[i] = *(const float4*)(rp[i] + k4 * 4);
        int idx = tid + i * 256;
        pw[i] = *(const float4*)(W + (size_t)(idx >> 5) * 4096 + nBase + (idx & 31) * 4);
    }

    for (int kt = 0; kt < 32; ++kt) {
#pragma unroll
        for (int i = 0; i < 4; ++i) {
            int idx = tid + i * 256;
            int m = idx >> 3;
            int cm = m >> 2;
            const float* e = (const float*)&pa[i];
#pragma unroll
            for (int r = 0; r < 4; ++r) {
                int k = k4 * 4 + r;
                As[k * 128 + ((cm ^ (k >> 2)) << 2) + (m & 3)] = e[r];
            }
            *(float4*)&Ws[(idx >> 5) * 128 + (idx & 31) * 4] = pw[i];
        }
        __syncthreads();
        if (kt + 1 < 32) {
            int kOff = (kt + 1) * 32;
#pragma unroll
            for (int i = 0; i < 4; ++i) {
                pa[i] = *(const float4*)(rp[i] + kOff + k4 * 4);
                int idx = tid + i * 256;
                pw[i] = *(const float4*)(W + (size_t)(kOff + (idx >> 5)) * 4096 + nBase + (idx & 31) * 4);
            }
        }
#pragma unroll
        for (int kk = 0; kk < 32; ++kk) {
            int sw = kk >> 2;
            ull a[4];
#pragma unroll
            for (int s = 0; s < 4; ++s) {
                int r = tyy + 16 * s;
                a[s] = *(const ull*)&As[kk * 128 + (((r >> 1) ^ sw) << 2) + 2 * (r & 1)];
            }
            float4 wA = *(const float4*)&Ws[kk * 128 + 8 * tx];
            float4 wB = *(const float4*)&Ws[kk * 128 + 8 * tx + 4];
            ull w[8];
            w[0] = dup2(wA.x); w[1] = dup2(wA.y); w[2] = dup2(wA.z); w[3] = dup2(wA.w);
            w[4] = dup2(wB.x); w[5] = dup2(wB.y); w[6] = dup2(wB.z); w[7] = dup2(wB.w);
#pragma unroll
            for (int s = 0; s < 4; ++s)
#pragma unroll
                for (int c = 0; c < 8; ++c)
                    fma2(acc[s][c], a[s], w[c]);
        }
        __syncthreads();
    }
    // direct store: C[((t*4096)+col)*64 + b], float2 over b-pair
#pragma unroll
    for (int s = 0; s < 4; ++s) {
        int r = tyy + 16 * s;
        int m = 2 * r;
        int b = m & 63, tsel = m >> 6;
        size_t tb = ((size_t)(2 * tp + tsel) * 4096 + nBase + 8 * tx) * 64 + b;
#pragma unroll
        for (int c = 0; c < 8; ++c) {
            float2 v = unpack2(acc[s][c]);
            *(float2*)&C[tb + (size_t)c * 64] = v;
        }
    }
}

// ---- fused transposes: z<4 gate-packed 4096-col, z==4 plain fc ----
__global__ void tposeAll(const float* __restrict__ eWih, const float* __restrict__ eWhh,
                         const float* __restrict__ dWih, const float* __restrict__ dWhh,
                         const float* __restrict__ fcW)
{
    __shared__ float t[32][33];
    int z = blockIdx.z;
    int k0 = blockIdx.x * 32, n0 = blockIdx.y * 32;
    if (z == 4) {
        if (blockIdx.y >= 32) return;
#pragma unroll
        for (int i = 0; i < 32; i += 8)
            t[threadIdx.y + i][threadIdx.x] = fcW[(size_t)(n0 + threadIdx.y + i) * 1024 + k0 + threadIdx.x];
        __syncthreads();
#pragma unroll
        for (int i = 0; i < 32; i += 8)
            g_WTfc[(size_t)(k0 + threadIdx.y + i) * 1024 + n0 + threadIdx.x] = t[threadIdx.x][threadIdx.y + i];
        return;
    }
    const float* src = (z == 0) ? eWih : (z == 1) ? eWhh : (z == 2) ? dWih : dWhh;
    float* dst = (z < 2) ? (g_WTenc + (size_t)(z & 1) * 1024 * 4096)
                         : (g_WTdec + (size_t)(z & 1) * 1024 * 4096);
#pragma unroll
    for (int i = 0; i < 32; i += 8) {
        int np  = n0 + threadIdx.y + i;
        int row = ((np & 3) << 10) + (np >> 2);
        t[threadIdx.y + i][threadIdx.x] = src[(size_t)row * 1024 + k0 + threadIdx.x];
    }
    __syncthreads();
#pragma unroll
    for (int i = 0; i < 32; i += 8)
        dst[(size_t)(k0 + threadIdx.y + i) * 4096 + n0 + threadIdx.x] = t[threadIdx.x][threadIdx.y + i];
}

// ---------------- init + mask decode (fused, 128x512) ----------------
__global__ void mask_init(const unsigned char* __restrict__ p,
                          const float* __restrict__ enc_b, const float* __restrict__ dec_b)
{
    int tid = threadIdx.x;
    int i = blockIdx.x * 512 + tid;     // 0..65535
    g_c[i] = 0.0f;
    g_dAT[0][i] = 0.0f;
    g_dAT[0][i + 65536] = 0.0f;
    if (i < 4096) {
        int row = ((i & 3) << 10) + (i >> 2);
        g_bpe[i] = enc_b[row];
        g_bpd[i] = dec_b[row];
    }
    if (blockIdx.x == 1) {
        g_barLeaf[tid] = 0u;              // 512 entries
        if (tid == 0) { g_barRoot = 0u; g_barGen = 0u; }
    }
    if (blockIdx.x == 0) {
        __shared__ int s_odd, s_big;
        if (tid == 0) { s_odd = 0; s_big = 0; }
        __syncthreads();
        unsigned char v = p[tid];
        if ((tid & 3) && v)  atomicOr(&s_odd, 1);
        if (v > 1)           atomicOr(&s_big, 1);
        __syncthreads();
        int m;
        if (s_big)        m = (((const float*)p)[tid] != 0.0f);
        else if (s_odd)   m = (p[tid] != 0);
        else              m = (((const int*)p)[tid] != 0);
        g_mask[tid] = m;
    }
}

// ---------------- host ----------------
extern "C" void kernel_launch(void* const* d_in, const int* in_sizes, int n_in,
                              void* d_out, int out_size)
{
    (void)in_sizes; (void)n_in; (void)out_size;
    const float* x       = (const float*)d_in[0];
    const float* target  = (const float*)d_in[1];
    const float* enc_Wih = (const float*)d_in[2];
    const float* enc_Whh = (const float*)d_in[3];
    const float* enc_b   = (const float*)d_in[4];
    const float* dec_Wih = (const float*)d_in[5];
    const float* dec_Whh = (const float*)d_in[6];
    const float* dec_b   = (const float*)d_in[7];
    const float* fc_W    = (const float*)d_in[8];
    const float* fc_b    = (const float*)d_in[9];
    const unsigned char* tf_mask = (const unsigned char*)d_in[10];
    float* out = (float*)d_out;

    float *pWTenc, *pGatesX;
    cudaGetSymbolAddress((void**)&pWTenc,  g_WTenc);
    cudaGetSymbolAddress((void**)&pGatesX, g_gatesX);

    // launch #1: init + mask decode
    mask_init<<<128, 512>>>(tf_mask, enc_b, dec_b);
    // launch #2: all five weight transposes
    tposeAll<<<dim3(32, 128, 5), dim3(32, 8)>>>(enc_Wih, enc_Whh, dec_Wih, dec_Whh, fc_W);
    // launch #3: gatesX[t][n'][b]  (128m x 128n tiles)
    gemm_pre<<<dim3(32, 256), 256>>>(x, pWTenc, pGatesX);
    // launch #4: the persistent recurrence (profiled by ncu -s 5 -c 1)
    seq2seq_persist<<<NBLK, 256>>>(x, target, fc_b, out);
}

// round 9
// speedup vs baseline: 1.0009x; 1.0009x over previous
#include <cuda_runtime.h>
#include <math.h>
#include <stdint.h>

typedef unsigned long long ull;

#define SS 512
#define NBLK 128

// ---------------- device scratch (no allocations allowed) ----------------
__device__ float g_WTenc[2048 * 4096];   // packed [k][n'=4j+g]; rows 0..1023 = Wih, 1024..2047 = Whh
__device__ float g_WTdec[2048 * 4096];   // same packing
__device__ float g_WTfc [1024 * 1024];   // plain [k][n]
__device__ float g_gatesX[(size_t)512 * 4096 * 64]; // [t][n'][b]  (512MB)
__device__ float g_dAT[2][2048 * 64];    // ping-pong, [k][b]: k 0..1023 = inp, 1024..2047 = h
__device__ float g_c  [1024 * 64];       // [j][b]
__device__ float g_partG[4][4096 * 64];  // gate partials [kz][n'][b]
__device__ float g_bpe[4096], g_bpd[4096];
__device__ int   g_mask[512];
__device__ unsigned           g_barLeaf[16 * 32];   // one leaf per 128B line
__device__ unsigned           g_barRoot;
__device__ volatile unsigned  g_barGen;

// ---------------- f32x2 helpers ----------------
__device__ __forceinline__ ull dup2(float v) {
    ull r; unsigned u = __float_as_uint(v);
    asm("mov.b64 %0, {%1, %1};" : "=l"(r) : "r"(u));
    return r;
}
__device__ __forceinline__ void fma2(ull& acc, ull a, ull b) {
    asm("fma.rn.f32x2 %0, %1, %2, %0;" : "+l"(acc) : "l"(a), "l"(b));
}
__device__ __forceinline__ ull add2(ull a, ull b) {
    ull r; asm("add.rn.f32x2 %0, %1, %2;" : "=l"(r) : "l"(a), "l"(b)); return r;
}
__device__ __forceinline__ float2 unpack2(ull v) {
    unsigned lo, hi;
    asm("mov.b64 {%0, %1}, %2;" : "=r"(lo), "=r"(hi) : "l"(v));
    return make_float2(__uint_as_float(lo), __uint_as_float(hi));
}
__device__ __forceinline__ float sigf(float x) { return 1.0f / (1.0f + expf(-x)); }

// ---------------- grid barrier: padded-leaf tree arrival + volatile poll ----------------
__device__ __forceinline__ void grid_sync(unsigned n) {
    __syncthreads();
    if (threadIdx.x == 0) {
        __threadfence();
        unsigned leaf = (blockIdx.x >> 3) * 32;          // 16 leaves, 128B apart
        if (atomicAdd(&g_barLeaf[leaf], 1u) + 1u == n * 8u) {
            if (atomicAdd(&g_barRoot, 1u) + 1u == n * 16u) {
                g_barGen = n;
            }
        }
        while (g_barGen < n) { }
        __threadfence();
    }
    __syncthreads();
}

// ============ gate GEMM: tile 64b x 128n, per-CTA K-slice, direct partial store ============
// 256 threads: ty=tid>>5 -> 8 b (4 pairs), tx=tid&31 -> 4 cols. 16 fma2/kk.
__device__ __forceinline__ void gemm_gate(const float* __restrict__ A,    // [k][64] at slice base
                                          const float* __restrict__ Wp,  // + row/col offsets, ldw 4096
                                          int nKT,
                                          float* As, float* Ws,
                                          float* __restrict__ dst,        // g_partG[kz] + p*128*64
                                          int tid)
{
    const int ty = tid >> 5, tx = tid & 31;
    ull acc[4][4];
#pragma unroll
    for (int q = 0; q < 4; ++q)
#pragma unroll
        for (int c = 0; c < 4; ++c) acc[q][c] = 0ull;

    float4 pa[2], pw[4];
#pragma unroll
    for (int i = 0; i < 2; ++i) {
        int idx = tid + i * 256;
        pa[i] = *(const float4*)(A + (size_t)(idx >> 4) * 64 + (idx & 15) * 4);
    }
#pragma unroll
    for (int i = 0; i < 4; ++i) {
        int idx = tid + i * 256;
        pw[i] = *(const float4*)(Wp + (size_t)(idx >> 5) * 4096 + (idx & 31) * 4);
    }

    for (int kt = 0; kt < nKT; ++kt) {
#pragma unroll
        for (int i = 0; i < 2; ++i) {
            int idx = tid + i * 256;
            *(float4*)&As[(idx >> 4) * 64 + (idx & 15) * 4] = pa[i];
        }
#pragma unroll
        for (int i = 0; i < 4; ++i) {
            int idx = tid + i * 256;
            *(float4*)&Ws[(idx >> 5) * 128 + (idx & 31) * 4] = pw[i];
        }
        __syncthreads();
        if (kt + 1 < nKT) {
            int kOff = (kt + 1) * 32;
#pragma unroll
            for (int i = 0; i < 2; ++i) {
                int idx = tid + i * 256;
                pa[i] = *(const float4*)(A + (size_t)(kOff + (idx >> 4)) * 64 + (idx & 15) * 4);
            }
#pragma unroll
            for (int i = 0; i < 4; ++i) {
                int idx = tid + i * 256;
                pw[i] = *(const float4*)(Wp + (size_t)(kOff + (idx >> 5)) * 4096 + (idx & 31) * 4);
            }
        }
#pragma unroll
        for (int kk = 0; kk < 32; ++kk) {
            ulonglong2 aa = *(const ulonglong2*)&As[kk * 64 + 8 * ty];
            ulonglong2 ab = *(const ulonglong2*)&As[kk * 64 + 8 * ty + 4];
            float4 wv = *(const float4*)&Ws[kk * 128 + 4 * tx];
            ull w0 = dup2(wv.x), w1 = dup2(wv.y), w2 = dup2(wv.z), w3 = dup2(wv.w);
            fma2(acc[0][0], aa.x, w0); fma2(acc[0][1], aa.x, w1);
            fma2(acc[0][2], aa.x, w2); fma2(acc[0][3], aa.x, w3);
            fma2(acc[1][0], aa.y, w0); fma2(acc[1][1], aa.y, w1);
            fma2(acc[1][2], aa.y, w2); fma2(acc[1][3], aa.y, w3);
            fma2(acc[2][0], ab.x, w0); fma2(acc[2][1], ab.x, w1);
            fma2(acc[2][2], ab.x, w2); fma2(acc[2][3], ab.x, w3);
            fma2(acc[3][0], ab.y, w0); fma2(acc[3][1], ab.y, w1);
            fma2(acc[3][2], ab.y, w2); fma2(acc[3][3], ab.y, w3);
        }
        __syncthreads();
    }
    // direct store: dst[(localcol)*64 + b], float2 over b-pair
#pragma unroll
    for (int q = 0; q < 4; ++q)
#pragma unroll
        for (int c = 0; c < 4; ++c) {
            float2 v = unpack2(acc[q][c]);
            *(float2*)&dst[(4 * tx + c) * 64 + 8 * ty + 2 * q] = v;
        }
}

// ============ fc GEMM full-K (64b x 8n per CTA) with fused select epilogue ============
__device__ __forceinline__ void fc_select(const float* __restrict__ A,   // h: [k][64], K=1024
                                          const float* __restrict__ Wp, // g_WTfc + bid*8
                                          const float* __restrict__ fc_b,
                                          const float* __restrict__ target,
                                          float* __restrict__ out,
                                          float* __restrict__ dA1,
                                          int t, int bid, int mk,
                                          float* As, float* Ws, int tid)
{
    const int ty = tid >> 3;   // b-pair 0..31
    const int tx = tid & 7;    // col
    ull acc[4];
#pragma unroll
    for (int i = 0; i < 4; ++i) acc[i] = 0ull;

    float4 pa[2], pw;
#pragma unroll
    for (int i = 0; i < 2; ++i) {
        int idx = tid + i * 256;
        pa[i] = *(const float4*)(A + (size_t)(idx >> 4) * 64 + (idx & 15) * 4);
    }
    if (tid < 64)
        pw = *(const float4*)(Wp + (size_t)(tid >> 1) * 1024 + (tid & 1) * 4);

    for (int kt = 0; kt < 32; ++kt) {
#pragma unroll
        for (int i = 0; i < 2; ++i) {
            int idx = tid + i * 256;
            *(float4*)&As[(idx >> 4) * 64 + (idx & 15) * 4] = pa[i];
        }
        if (tid < 64) *(float4*)&Ws[(tid >> 1) * 8 + (tid & 1) * 4] = pw;
        __syncthreads();
        if (kt + 1 < 32) {
            int kOff = (kt + 1) * 32;
#pragma unroll
            for (int i = 0; i < 2; ++i) {
                int idx = tid + i * 256;
                pa[i] = *(const float4*)(A + (size_t)(kOff + (idx >> 4)) * 64 + (idx & 15) * 4);
            }
            if (tid < 64)
                pw = *(const float4*)(Wp + (size_t)(kOff + (tid >> 1)) * 1024 + (tid & 1) * 4);
        }
#pragma unroll
        for (int kk = 0; kk < 32; ++kk) {
            ull a = *(const ull*)&As[kk * 64 + 2 * ty];
            fma2(acc[kk & 3], a, dup2(Ws[kk * 8 + tx]));
        }
        __syncthreads();
    }
    ull s = add2(add2(acc[0], acc[1]), add2(acc[2], acc[3]));
    float2 v = unpack2(s);
    int n = bid * 8 + tx;
    float vb = fc_b[n];
    int b0 = 2 * ty;
    float p0 = v.x + vb, p1 = v.y + vb;
    size_t o0 = ((size_t)b0 * SS + t) * 1024 + n;
    size_t o1 = o0 + (size_t)SS * 1024;
    out[o0] = p0;
    out[o1] = p1;
    dA1[n * 64 + b0]     = mk ? target[o0] : p0;
    dA1[n * 64 + b0 + 1] = mk ? target[o1] : p1;
}

// ============ the persistent seq2seq kernel ============
__global__ __launch_bounds__(256, 1)
void seq2seq_persist(const float* __restrict__ x, const float* __restrict__ target,
                     const float* __restrict__ fc_b, float* __restrict__ out)
{
    __shared__ __align__(16) float As[32 * 64];
    __shared__ __align__(16) float Ws[32 * 128];

    const int tid = threadIdx.x;
    const int bid = blockIdx.x;
    const int p   = bid >> 2;     // n-tile (128 cols)
    const int kz  = bid & 3;      // K quarter
    int cur = 0;
    unsigned ns = 0;

    // ---------------- encoder (gate K=1024, h only; x-part precomputed) ----------------
    for (int t = 0; t < SS; ++t) {
        gemm_gate(g_dAT[cur] + (size_t)(1024 + kz * 256) * 64,
                  g_WTenc + (size_t)(1024 + kz * 256) * 4096 + p * 128,
                  8, As, Ws, g_partG[kz] + (size_t)p * 128 * 64, tid);
        grid_sync(++ns);
#pragma unroll
        for (int r = 0; r < 2; ++r) {
            int id = tid + 256 * r;
            int b = id & 63, jj = id >> 6;
            int np = bid * 32 + 4 * jj;
            int j  = bid * 8 + jj;
            const float* q0 = g_partG[0] + (size_t)np * 64 + b;
            const float* q1 = g_partG[1] + (size_t)np * 64 + b;
            const float* q2 = g_partG[2] + (size_t)np * 64 + b;
            const float* q3 = g_partG[3] + (size_t)np * 64 + b;
            const float* gx = g_gatesX + ((size_t)t * 4096 + np) * 64 + b;
            float4 bb = *(const float4*)&g_bpe[np];
            float gi = q0[0]   + q1[0]   + q2[0]   + q3[0]   + gx[0]   + bb.x;
            float gf = q0[64]  + q1[64]  + q2[64]  + q3[64]  + gx[64]  + bb.y;
            float gg = q0[128] + q1[128] + q2[128] + q3[128] + gx[128] + bb.z;
            float go = q0[192] + q1[192] + q2[192] + q3[192] + gx[192] + bb.w;
            float c  = g_c[j * 64 + b];
            float cn = sigf(gf) * c + sigf(gi) * tanhf(gg);
            float hn = sigf(go) * tanhf(cn);
            g_c[j * 64 + b] = cn;
            g_dAT[cur ^ 1][(1024 + j) * 64 + b] = hn;
            if (t == SS - 1)   // stage dec_inp0 = x[:, -1, :]
                g_dAT[cur ^ 1][j * 64 + b] = x[((size_t)b * SS + SS - 1) * 1024 + j];
        }
        grid_sync(++ns);
        cur ^= 1;
    }

    // ---------------- decoder (gate K=2048) ----------------
    for (int t = 0; t < SS; ++t) {
        gemm_gate(g_dAT[cur] + (size_t)(kz * 512) * 64,
                  g_WTdec + (size_t)(kz * 512) * 4096 + p * 128,
                  16, As, Ws, g_partG[kz] + (size_t)p * 128 * 64, tid);
        grid_sync(++ns);
#pragma unroll
        for (int r = 0; r < 2; ++r) {
            int id = tid + 256 * r;
            int b = id & 63, jj = id >> 6;
            int np = bid * 32 + 4 * jj;
            int j  = bid * 8 + jj;
            const float* q0 = g_partG[0] + (size_t)np * 64 + b;
            const float* q1 = g_partG[1] + (size_t)np * 64 + b;
            const float* q2 = g_partG[2] + (size_t)np * 64 + b;
            const float* q3 = g_partG[3] + (size_t)np * 64 + b;
            float4 bb = *(const float4*)&g_bpd[np];
            float gi = q0[0]   + q1[0]   + q2[0]   + q3[0]   + bb.x;
            float gf = q0[64]  + q1[64]  + q2[64]  + q3[64]  + bb.y;
            float gg = q0[128] + q1[128] + q2[128] + q3[128] + bb.z;
            float go = q0[192] + q1[192] + q2[192] + q3[192] + bb.w;
            float c  = g_c[j * 64 + b];
            float cn = sigf(gf) * c + sigf(gi) * tanhf(gg);
            float hn = sigf(go) * tanhf(cn);
            g_c[j * 64 + b] = cn;
            g_dAT[cur ^ 1][(1024 + j) * 64 + b] = hn;
        }
        grid_sync(++ns);   // h complete before fc reads full K
        fc_select(g_dAT[cur ^ 1] + (size_t)1024 * 64, g_WTfc + bid * 8,
                  fc_b, target, out, g_dAT[cur ^ 1], t, bid, g_mask[t], As, Ws, tid);
        grid_sync(++ns);   // inp visible before next gate GEMM
        cur ^= 1;
    }
}

// ============ pre-GEMM: gatesX[t][n'][b] = x[b,t,:] @ packed Wih^T ============
// tile 128m x 128n (m = 2 timesteps x 64 batch), per-thread 8x8 = 32 fma2/kk
__global__ __launch_bounds__(256, 1)
void gemm_pre(const float* __restrict__ x, const float* __restrict__ W,
              float* __restrict__ C)
{
    __shared__ __align__(16) float As[32 * 128];   // [k][m] swizzled
    __shared__ __align__(16) float Ws[32 * 128];   // [k][n]

    const int tid = threadIdx.x;
    const int nBase = blockIdx.x * 128;
    const int tp    = blockIdx.y;          // t-pair
    const int tyy = tid >> 4;              // 0..15 -> pairs {tyy, tyy+16, tyy+32, tyy+48}
    const int tx  = tid & 15;              // cols 8*tx .. 8*tx+7

    ull acc[4][8];
#pragma unroll
    for (int s = 0; s < 4; ++s)
#pragma unroll
        for (int c = 0; c < 8; ++c) acc[s][c] = 0ull;

    // row pointers for the 4 A-load rows this thread stages
    const float* rp[4];
#pragma unroll
    for (int i = 0; i < 4; ++i) {
        int idx = tid + i * 256;
        int mA = idx >> 3;
        int b = mA & 63, tsel = mA >> 6;
        rp[i] = x + ((size_t)b * SS + 2 * tp + tsel) * 1024;
    }
    const int k4 = tid & 7;

    float4 pa[4], pw[4];
#pragma unroll
    for (int i = 0; i < 4; ++i) {
        pa[i] = *(const float4*)(rp[i] + k4 * 4);
        int idx = tid + i * 256;
        pw[i] = *(const float4*)(W + (size_t)(idx >> 5) * 4096 + nBase + (idx & 31) * 4);
    }

    for (int kt = 0; kt < 32; ++kt) {
#pragma unroll
        for (int i = 0; i < 4; ++i) {
            int idx = tid + i * 256;
            int m = idx >> 3;
            int cm = m >> 2;
            const float* e = (const float*)&pa[i];
#pragma unroll
            for (int r = 0; r < 4; ++r) {
                int k = k4 * 4 + r;
                As[k * 128 + ((cm ^ (k >> 2)) << 2) + (m & 3)] = e[r];
            }
            *(float4*)&Ws[(idx >> 5) * 128 + (idx & 31) * 4] = pw[i];
        }
        __syncthreads();
        if (kt + 1 < 32) {
            int kOff = (kt + 1) * 32;
#pragma unroll
            for (int i = 0; i < 4; ++i) {
                pa[i] = *(const float4*)(rp[i] + kOff + k4 * 4);
                int idx = tid + i * 256;
                pw[i] = *(const float4*)(W + (size_t)(kOff + (idx >> 5)) * 4096 + nBase + (idx & 31) * 4);
            }
        }
#pragma unroll
        for (int kk = 0; kk < 32; ++kk) {
            int sw = kk >> 2;
            ull a[4];
#pragma unroll
            for (int s = 0; s < 4; ++s) {
                int r = tyy + 16 * s;
                a[s] = *(const ull*)&As[kk * 128 + (((r >> 1) ^ sw) << 2) + 2 * (r & 1)];
            }
            float4 wA = *(const float4*)&Ws[kk * 128 + 8 * tx];
            float4 wB = *(const float4*)&Ws[kk * 128 + 8 * tx + 4];
            ull w[8];
            w[0] = dup2(wA.x); w[1] = dup2(wA.y); w[2] = dup2(wA.z); w[3] = dup2(wA.w);
            w[4] = dup2(wB.x); w[5] = dup2(wB.y); w[6] = dup2(wB.z); w[7] = dup2(wB.w);
#pragma unroll
            for (int s = 0; s < 4; ++s)
#pragma unroll
                for (int c = 0; c < 8; ++c)
                    fma2(acc[s][c], a[s], w[c]);
        }
        __syncthreads();
    }
    // direct store: C[((t*4096)+col)*64 + b], float2 over b-pair
#pragma unroll
    for (int s = 0; s < 4; ++s) {
        int r = tyy + 16 * s;
        int m = 2 * r;
        int b = m & 63, tsel = m >> 6;
        size_t tb = ((size_t)(2 * tp + tsel) * 4096 + nBase + 8 * tx) * 64 + b;
#pragma unroll
        for (int c = 0; c < 8; ++c) {
            float2 v = unpack2(acc[s][c]);
            *(float2*)&C[tb + (size_t)c * 64] = v;
        }
    }
}

// ---- fused transposes: z<4 gate-packed 4096-col, z==4 plain fc ----
__global__ void tposeAll(const float* __restrict__ eWih, const float* __restrict__ eWhh,
                         const float* __restrict__ dWih, const float* __restrict__ dWhh,
                         const float* __restrict__ fcW)
{
    __shared__ float t[32][33];
    int z = blockIdx.z;
    int k0 = blockIdx.x * 32, n0 = blockIdx.y * 32;
    if (z == 4) {
        if (blockIdx.y >= 32) return;
#pragma unroll
        for (int i = 0; i < 32; i += 8)
            t[threadIdx.y + i][threadIdx.x] = fcW[(size_t)(n0 + threadIdx.y + i) * 1024 + k0 + threadIdx.x];
        __syncthreads();
#pragma unroll
        for (int i = 0; i < 32; i += 8)
            g_WTfc[(size_t)(k0 + threadIdx.y + i) * 1024 + n0 + threadIdx.x] = t[threadIdx.x][threadIdx.y + i];
        return;
    }
    const float* src = (z == 0) ? eWih : (z == 1) ? eWhh : (z == 2) ? dWih : dWhh;
    float* dst = (z < 2) ? (g_WTenc + (size_t)(z & 1) * 1024 * 4096)
                         : (g_WTdec + (size_t)(z & 1) * 1024 * 4096);
#pragma unroll
    for (int i = 0; i < 32; i += 8) {
        int np  = n0 + threadIdx.y + i;
        int row = ((np & 3) << 10) + (np >> 2);
        t[threadIdx.y + i][threadIdx.x] = src[(size_t)row * 1024 + k0 + threadIdx.x];
    }
    __syncthreads();
#pragma unroll
    for (int i = 0; i < 32; i += 8)
        dst[(size_t)(k0 + threadIdx.y + i) * 4096 + n0 + threadIdx.x] = t[threadIdx.x][threadIdx.y + i];
}

// ---------------- init + mask decode (fused, 128x512) ----------------
__global__ void mask_init(const unsigned char* __restrict__ p,
                          const float* __restrict__ enc_b, const float* __restrict__ dec_b)
{
    int tid = threadIdx.x;
    int i = blockIdx.x * 512 + tid;     // 0..65535
    g_c[i] = 0.0f;
    g_dAT[0][i] = 0.0f;
    g_dAT[0][i + 65536] = 0.0f;
    if (i < 4096) {
        int row = ((i & 3) << 10) + (i >> 2);
        g_bpe[i] = enc_b[row];
        g_bpd[i] = dec_b[row];
    }
    if (blockIdx.x == 1) {
        g_barLeaf[tid] = 0u;              // 512 entries
        if (tid == 0) { g_barRoot = 0u; g_barGen = 0u; }
    }
    if (blockIdx.x == 0) {
        __shared__ int s_odd, s_big;
        if (tid == 0) { s_odd = 0; s_big = 0; }
        __syncthreads();
        unsigned char v = p[tid];
        if ((tid & 3) && v)  atomicOr(&s_odd, 1);
        if (v > 1)           atomicOr(&s_big, 1);
        __syncthreads();
        int m;
        if (s_big)        m = (((const float*)p)[tid] != 0.0f);
        else if (s_odd)   m = (p[tid] != 0);
        else              m = (((const int*)p)[tid] != 0);
        g_mask[tid] = m;
    }
}

// ---------------- host ----------------
extern "C" void kernel_launch(void* const* d_in, const int* in_sizes, int n_in,
                              void* d_out, int out_size)
{
    (void)in_sizes; (void)n_in; (void)out_size;
    const float* x       = (const float*)d_in[0];
    const float* target  = (const float*)d_in[1];
    const float* enc_Wih = (const float*)d_in[2];
    const float* enc_Whh = (const float*)d_in[3];
    const float* enc_b   = (const float*)d_in[4];
    const float* dec_Wih = (const float*)d_in[5];
    const float* dec_Whh = (const float*)d_in[6];
    const float* dec_b   = (const float*)d_in[7];
    const float* fc_W    = (const float*)d_in[8];
    const float* fc_b    = (const float*)d_in[9];
    const unsigned char* tf_mask = (const unsigned char*)d_in[10];
    float* out = (float*)d_out;

    float *pWTenc, *pGatesX;
    cudaGetSymbolAddress((void**)&pWTenc,  g_WTenc);
    cudaGetSymbolAddress((void**)&pGatesX, g_gatesX);

    // launch #1: init + mask decode
    mask_init<<<128, 512>>>(tf_mask, enc_b, dec_b);
    // launch #2: all five weight transposes
    tposeAll<<<dim3(32, 128, 5), dim3(32, 8)>>>(enc_Wih, enc_Whh, dec_Wih, dec_Whh, fc_W);
    // launch #3: gatesX[t][n'][b]  (128m x 128n tiles)
    gemm_pre<<<dim3(32, 256), 256>>>(x, pWTenc, pGatesX);
    // launch #4: the persistent recurrence (profiled by ncu -s 5 -c 1)
    seq2seq_persist<<<NBLK, 256>>>(x, target, fc_b, out);
}